// round 6
// baseline (speedup 1.0000x reference)
#include <cuda_runtime.h>
#include <cstdint>

// ROUND 6 = third resubmission of the push/mailbox kernel (R3, R4, R5 benches
// all lost to GPU-broker acquisition timeouts; still zero measurements).
// Single hypothesis under test, unchanged: pull-poll exchange (32 hot cache
// lines, LTS-slice saturated at ~53 B/cyc demand vs ~33 B/cyc capacity)
// -> push/private-mailbox exchange (1 MB spread over ~192 slices, unsaturated).
// Predicted: 19.09 ms -> 10-13 ms, rel_err identical (5.2e-07).

// Problem constants
#define T_LEN   16384
#define NXD     128
#define NHD     512
#define STEPS   (T_LEN - NXD)   // 16256
#define G       128             // persistent CTAs (all co-resident on 148 SMs)
#define UPC     4               // hidden units per CTA (NHD / G)
#define ROWS    16              // 4 gates * UPC
#define NTHR    256
#define SMEM_FLOATS (T_LEN + NHD + ROWS)

// Push mailboxes: per-consumer private copy of the full tagged h vector.
// word = (tag << 32) | float_bits(h). g_mbox[phase][consumer][unit]
__device__ unsigned long long g_mbox[2][G][NHD];
// Per-(step, cta) partial of Ahy @ h
__device__ float g_partials[STEPS * G];

__device__ __forceinline__ float fsigmoid(float x) {
    x = fminf(fmaxf(x, -30.f), 30.f);
    return __fdividef(1.f, 1.f + __expf(-x));
}
__device__ __forceinline__ float ftanh_fast(float x) {
    x = fminf(fmaxf(x, -15.f), 15.f);
    float e = __expf(2.f * x);
    return __fdividef(e - 1.f, e + 1.f);
}

__device__ __forceinline__ void ld_vol_v2(const unsigned long long* p,
                                          unsigned long long& a, unsigned long long& b) {
    asm volatile("ld.volatile.global.v2.u64 {%0,%1}, [%2];"
                 : "=l"(a), "=l"(b) : "l"(p) : "memory");
}
__device__ __forceinline__ void st_vol_v2(unsigned long long* p,
                                          unsigned long long a, unsigned long long b) {
    asm volatile("st.volatile.global.v2.u64 [%0], {%1,%2};"
                 :: "l"(p), "l"(a), "l"(b) : "memory");
}

// Zero all mailbox tags each run (tag 0 / h=0.0 is the step-0 initial state).
__global__ void rnn_clear_kernel() {
    unsigned long long* p = &g_mbox[0][0][0];
    const int n = 2 * G * NHD;
    for (int i = blockIdx.x * blockDim.x + threadIdx.x; i < n; i += gridDim.x * blockDim.x)
        p[i] = 0ULL;
}

// No-op spacer so ncu (-s 5 -c 1) profiles the scan kernel.
__global__ void rnn_nop_kernel() {}

__global__ __launch_bounds__(NTHR, 1) void rnn_scan_kernel(
    const float* __restrict__ x,
    const float* __restrict__ Wf, const float* __restrict__ Uf, const float* __restrict__ bf,
    const float* __restrict__ Wi, const float* __restrict__ Ui, const float* __restrict__ bi,
    const float* __restrict__ Wo, const float* __restrict__ Uo, const float* __restrict__ bo,
    const float* __restrict__ Wc, const float* __restrict__ Uc, const float* __restrict__ bc,
    const float* __restrict__ Ahy)
{
    extern __shared__ float smem[];
    float* x_s = smem;              // [T_LEN]
    float* h_s = x_s + T_LEN;       // [NHD]
    float* a_s = h_s + NHD;         // [ROWS] activated gate values
    __shared__ unsigned long long pk_s[UPC];   // packed (tag|h) words to fan out

    const int tid = threadIdx.x;
    const int cta = blockIdx.x;
    const int w   = tid >> 5;
    const int l   = tid & 31;

    // Stage full x into smem (one time).
    for (int i = tid; i < T_LEN / 4; i += NTHR)
        reinterpret_cast<float4*>(x_s)[i] = reinterpret_cast<const float4*>(x)[i];

    const float* Uarr[4] = {Uf, Ui, Uo, Uc};
    const float* Warr[4] = {Wf, Wi, Wo, Wc};
    const float* barr[4] = {bf, bi, bo, bc};

    // Each warp owns 2 rows. Row r: gate = r>>2, unit = r&3 (global j = cta*UPC + unit).
    const int r0 = 2 * w,      r1 = 2 * w + 1;
    const int g0 = r0 >> 2,    u0 = r0 & 3;
    const int g1 = r1 >> 2,    u1 = r1 & 3;
    const int j0 = cta * UPC + u0;
    const int j1 = cta * UPC + u1;
    const bool gate_is_tanh = (g0 == 3);

    // Weights live in registers for the whole run.
    float4 uw0[4], uw1[4];
#pragma unroll
    for (int i = 0; i < 4; ++i) {
        uw0[i] = reinterpret_cast<const float4*>(Uarr[g0] + (size_t)j0 * NHD)[32 * i + l];
        uw1[i] = reinterpret_cast<const float4*>(Uarr[g1] + (size_t)j1 * NHD)[32 * i + l];
    }
    float4 ww0 = reinterpret_cast<const float4*>(Warr[g0] + (size_t)j0 * NXD)[l];
    float4 ww1 = reinterpret_cast<const float4*>(Warr[g1] + (size_t)j1 * NXD)[l];
    const float b0 = barr[g0][j0];
    const float b1 = barr[g1][j1];

    // Threads 0..3 carry c-state in a register; also cache their Ahy element.
    float cstate = 0.f;
    float ahy = 0.f;
    if (tid < UPC) ahy = Ahy[cta * UPC + tid];

    __syncthreads();

    // Fanout targets: thread i serves consumer i>>1, half i&1.
    const int f_c    = tid >> 1;
    const int f_half = tid & 1;

    for (int t = 0; t < STEPS; ++t) {
        // ---- first poll of OWN mailbox issued immediately (one 16B load) ----
        unsigned long long* mb = &g_mbox[t & 1][cta][0] + 2 * tid;
        const unsigned want = (unsigned)t;
        unsigned long long va, vb;
        ld_vol_v2(mb, va, vb);

        // ---- x-window part computed in the shadow of the poll load ----
        const float* xs = x_s + t + 4 * l;
        float xv0 = xs[0], xv1 = xs[1], xv2 = xs[2], xv3 = xs[3];
        float acc0 = ww0.x * xv0 + ww0.y * xv1 + ww0.z * xv2 + ww0.w * xv3;
        float acc1 = ww1.x * xv0 + ww1.y * xv1 + ww1.z * xv2 + ww1.w * xv3;

        // ---- spin until both tagged words are current ----
        while ((unsigned)(va >> 32) != want || (unsigned)(vb >> 32) != want)
            ld_vol_v2(mb, va, vb);
        h_s[2 * tid]     = __uint_as_float((unsigned)va);
        h_s[2 * tid + 1] = __uint_as_float((unsigned)vb);
        __syncthreads();   // h_s staged

        // ---- U @ h (weights in regs, h from smem, vectorized) ----
#pragma unroll
        for (int i = 0; i < 4; ++i) {
            float4 h4 = reinterpret_cast<float4*>(h_s)[32 * i + l];
            acc0 += uw0[i].x * h4.x + uw0[i].y * h4.y + uw0[i].z * h4.z + uw0[i].w * h4.w;
            acc1 += uw1[i].x * h4.x + uw1[i].y * h4.y + uw1[i].z * h4.z + uw1[i].w * h4.w;
        }

        // ---- warp butterfly reduce both rows ----
#pragma unroll
        for (int o = 16; o; o >>= 1) {
            acc0 += __shfl_xor_sync(0xFFFFFFFFu, acc0, o);
            acc1 += __shfl_xor_sync(0xFFFFFFFFu, acc1, o);
        }

        // ---- activation at the owner lanes (16 activations in parallel) ----
        if (l < 2) {
            float acc = (l == 0) ? (acc0 + b0) : (acc1 + b1);
            float a   = gate_is_tanh ? ftanh_fast(acc) : fsigmoid(acc);
            a_s[(l == 0) ? r0 : r1] = a;
        }
        __syncthreads();   // a_s ready

        // ---- state update (threads 0..3) + pack for fanout ----
        float hn_local = 0.f;
        if (tid < UPC) {
            const int u = tid;
            float f  = a_s[0  + u];
            float in = a_s[4  + u];
            float o  = a_s[8  + u];
            float gg = a_s[12 + u];
            cstate = f * cstate + in * gg;
            hn_local = o * ftanh_fast(cstate);
            pk_s[u] = ((unsigned long long)(unsigned)(t + 1) << 32)
                    | (unsigned long long)__float_as_uint(hn_local);
        }
        __syncthreads();   // pk_s ready

        // ---- push fanout: every thread fires one 16B store to one consumer ----
        {
            unsigned long long p0 = pk_s[2 * f_half];
            unsigned long long p1 = pk_s[2 * f_half + 1];
            unsigned long long* dst = &g_mbox[(t + 1) & 1][f_c][4 * cta + 2 * f_half];
            st_vol_v2(dst, p0, p1);
        }

        // ---- mu partial — off the critical path ----
        if (tid < UPC) {
            float pm = ahy * hn_local;
            pm += __shfl_xor_sync(0xFu, pm, 1);
            pm += __shfl_xor_sync(0xFu, pm, 2);
            if (tid == 0) g_partials[(size_t)t * G + cta] = pm;
        }
    }
}

// out[t] = by + sum_c partials[t][c]
__global__ void rnn_reduce_kernel(const float* __restrict__ by, float* __restrict__ out) {
    const int t = blockIdx.x;
    float v = g_partials[(size_t)t * G + threadIdx.x];
#pragma unroll
    for (int o = 16; o; o >>= 1) v += __shfl_xor_sync(0xFFFFFFFFu, v, o);
    __shared__ float s[4];
    if ((threadIdx.x & 31) == 0) s[threadIdx.x >> 5] = v;
    __syncthreads();
    if (threadIdx.x == 0) out[t] = s[0] + s[1] + s[2] + s[3] + by[0];
}

extern "C" void kernel_launch(void* const* d_in, const int* in_sizes, int n_in,
                              void* d_out, int out_size) {
    (void)in_sizes; (void)n_in; (void)out_size;
    const float* x   = (const float*)d_in[0];
    const float* Wf  = (const float*)d_in[1];
    const float* Uf  = (const float*)d_in[2];
    const float* bf  = (const float*)d_in[3];
    const float* Wi  = (const float*)d_in[4];
    const float* Ui  = (const float*)d_in[5];
    const float* bi  = (const float*)d_in[6];
    const float* Wo  = (const float*)d_in[7];
    const float* Uo  = (const float*)d_in[8];
    const float* bo  = (const float*)d_in[9];
    const float* Wc  = (const float*)d_in[10];
    const float* Uc  = (const float*)d_in[11];
    const float* bc  = (const float*)d_in[12];
    const float* Ahy = (const float*)d_in[13];
    const float* by  = (const float*)d_in[14];
    float* out = (float*)d_out;

    const int smem_bytes = SMEM_FLOATS * (int)sizeof(float);
    cudaFuncSetAttribute(rnn_scan_kernel, cudaFuncAttributeMaxDynamicSharedMemorySize, smem_bytes);

    // Launch order puts the scan kernel at index 5 so ncu (-s 5 -c 1) profiles it.
    rnn_clear_kernel<<<256, 512>>>();
    rnn_nop_kernel<<<1, 32>>>();
    rnn_nop_kernel<<<1, 32>>>();
    rnn_nop_kernel<<<1, 32>>>();
    rnn_nop_kernel<<<1, 32>>>();
    rnn_scan_kernel<<<G, NTHR, smem_bytes>>>(x, Wf, Uf, bf, Wi, Ui, bi,
                                             Wo, Uo, bo, Wc, Uc, bc, Ahy);
    rnn_reduce_kernel<<<STEPS, G>>>(by, out);
}